// round 5
// baseline (speedup 1.0000x reference)
#include <cuda_runtime.h>

// Problem shape (fixed by the dataset)
#define BB 4
#define SS 256
#define EE 256
#define MM (BB * SS)

// Scratch + sync state
__device__ float g_pi [MM * EE];
__device__ float g_pjb[MM * EE];
__device__ volatile int g_arrive;
__device__ unsigned g_exit;

#define NBLK 256            // persistent grid: <=2 CTAs/SM, always fully resident

// ---- gemm phase config: 256 tiles, one per block ----
#define BM 16
#define BN 64
#define BK 32
#define NT (EE / BK)        // 8 K-chunks
#define XS 20               // s_x row stride (floats)
#define WS 68               // s_w row stride (floats), 272B = 16B-aligned

// ---- add phase config ----
#define TI 8
#define TJ 32
#define E4 (EE / 4)

union Smem {
    struct {
        float x [BK][XS];   // 2.5 KB
        float w1[BK][WS];   // 8.7 KB
        float w2[BK][WS];   // 8.7 KB
    } g;
    float4 pj[TJ * E4];     // 32 KB
};

__device__ __forceinline__ void fma2(unsigned long long& acc,
                                     unsigned long long a,
                                     unsigned long long b)
{
    asm("fma.rn.f32x2 %0, %1, %2, %0;" : "+l"(acc) : "l"(a), "l"(b));
}

__device__ __forceinline__ unsigned long long bcast2(float a)
{
    unsigned long long r;
    asm("mov.b64 %0, {%1, %1};" : "=l"(r) : "r"(__float_as_int(a)));
    return r;
}

__global__ __launch_bounds__(256)
void fused_kernel(const float* __restrict__ x,
                  const float* __restrict__ W,
                  const float* __restrict__ bias,
                  float* __restrict__ out)
{
    __shared__ Smem sm;
    const int tid = threadIdx.x;
    const int bid = blockIdx.x;

    // ================= PHASE 1: dual GEMM (one BM x BN tile per block) =====
    //   pi[m,f]  = sum_e x[m,e] * W[f,e]
    //   pjb[m,f] = sum_e x[m,e] * W[f,EE+e] + b[f]
    {
        const int f0 = (bid & 3) * BN;
        const int m0 = (bid >> 2) * BM;

        const int  lkv   = tid & 7;        // k-float4 within chunk
        const int  lm    = tid >> 3;       // x row (tid<128 only)
        const int  lf    = tid >> 3;       // W row base (0..31; +32 for r=1)
        const bool xload = (tid < 128);

        const int m  = tid >> 4;           // 0..15 output m row
        const int fx = tid & 15;           // output f group (4 floats)

        float4 rx = make_float4(0.f, 0.f, 0.f, 0.f);
        float4 rw1[2], rw2[2];

        // prologue: chunk 0 -> regs
        if (xload)
            rx = *(const float4*)&x[(size_t)(m0 + lm) * EE + lkv * 4];
        #pragma unroll
        for (int r = 0; r < 2; ++r) {
            const float* wrow = W + (size_t)(f0 + lf + r * 32) * (2 * EE) + lkv * 4;
            rw1[r] = *(const float4*)(wrow);
            rw2[r] = *(const float4*)(wrow + EE);
        }

        unsigned long long acc[4] = {0ull, 0ull, 0ull, 0ull};
        // acc[0..1]: matrix1 f-pairs (f0..f1, f2..f3); acc[2..3]: matrix2

        for (int t = 0; t < NT; ++t) {
            // drain prefetch regs into smem
            if (t > 0) __syncthreads();      // previous chunk's readers done
            if (xload) {
                sm.g.x[lkv * 4 + 0][lm] = rx.x;
                sm.g.x[lkv * 4 + 1][lm] = rx.y;
                sm.g.x[lkv * 4 + 2][lm] = rx.z;
                sm.g.x[lkv * 4 + 3][lm] = rx.w;
            }
            #pragma unroll
            for (int r = 0; r < 2; ++r) {
                int f = lf + r * 32;
                sm.g.w1[lkv * 4 + 0][f] = rw1[r].x;
                sm.g.w1[lkv * 4 + 1][f] = rw1[r].y;
                sm.g.w1[lkv * 4 + 2][f] = rw1[r].z;
                sm.g.w1[lkv * 4 + 3][f] = rw1[r].w;
                sm.g.w2[lkv * 4 + 0][f] = rw2[r].x;
                sm.g.w2[lkv * 4 + 1][f] = rw2[r].y;
                sm.g.w2[lkv * 4 + 2][f] = rw2[r].z;
                sm.g.w2[lkv * 4 + 3][f] = rw2[r].w;
            }
            __syncthreads();

            // prefetch next chunk (LDGs issued before compute)
            if (t + 1 < NT) {
                const int k0 = (t + 1) * BK;
                if (xload)
                    rx = *(const float4*)&x[(size_t)(m0 + lm) * EE + k0 + lkv * 4];
                #pragma unroll
                for (int r = 0; r < 2; ++r) {
                    const float* wrow = W + (size_t)(f0 + lf + r * 32) * (2 * EE) + k0 + lkv * 4;
                    rw1[r] = *(const float4*)(wrow);
                    rw2[r] = *(const float4*)(wrow + EE);
                }
            }

            // compute: packed f32x2 FMA (2 MACs per issue)
            #pragma unroll
            for (int k = 0; k < BK; ++k) {
                unsigned long long aa = bcast2(sm.g.x[k][m]);
                const ulonglong2 b1 = *(const ulonglong2*)&sm.g.w1[k][fx * 4];
                const ulonglong2 b2 = *(const ulonglong2*)&sm.g.w2[k][fx * 4];
                fma2(acc[0], aa, b1.x);
                fma2(acc[1], aa, b1.y);
                fma2(acc[2], aa, b2.x);
                fma2(acc[3], aa, b2.y);
            }
        }

        // epilogue: unpack, add bias to matrix2, store
        float2 a0 = *(float2*)&acc[0];
        float2 a1 = *(float2*)&acc[1];
        float2 a2 = *(float2*)&acc[2];
        float2 a3 = *(float2*)&acc[3];
        float4 bi = *(const float4*)&bias[f0 + fx * 4];

        const size_t o = (size_t)(m0 + m) * EE + f0 + fx * 4;
        *(float4*)&g_pi [o] = make_float4(a0.x, a0.y, a1.x, a1.y);
        *(float4*)&g_pjb[o] = make_float4(a2.x + bi.x, a2.y + bi.y,
                                          a3.x + bi.z, a3.y + bi.w);
    }

    // ================= global barrier (all 256 blocks resident) ============
    __threadfence();
    __syncthreads();
    if (tid == 0) {
        atomicAdd((int*)&g_arrive, 1);
        int ns = 32;
        while (g_arrive < NBLK) {
            __nanosleep(ns);
            if (ns < 1024) ns <<= 1;
        }
    }
    __syncthreads();
    __threadfence();   // acquire

    // ================= PHASE 2: broadcast add =============================
    // Block's 4 jobs share (b, i0): pi stays in registers, pj restaged per job.
    {
        const int b  = bid >> 6;
        const int i0 = ((bid >> 1) & 31) * TI;
        const int e4 = tid & 63;
        const int jq = tid >> 6;

        const float4* pi4 = (const float4*)g_pi + (size_t)(b * SS + i0) * E4;
        float4 pi_r[TI];
        #pragma unroll
        for (int i = 0; i < TI; ++i)
            pi_r[i] = pi4[i * E4 + e4];

        #pragma unroll
        for (int q = 0; q < 4; ++q) {
            const int j0 = ((bid & 1) * 4 + q) * TJ;

            __syncthreads();   // previous readers of sm.pj done
            const float4* pj4 = (const float4*)g_pjb + (size_t)(b * SS + j0) * E4;
            #pragma unroll
            for (int r = 0; r < 8; ++r)
                sm.pj[tid + r * 256] = pj4[tid + r * 256];
            __syncthreads();

            float4* out4 = (float4*)out + ((size_t)(b * SS + i0) * SS + j0) * E4;
            #pragma unroll
            for (int jj = 0; jj < TJ / 4; ++jj) {
                int j = jq + jj * 4;
                float4 c = sm.pj[j * E4 + e4];
                #pragma unroll
                for (int i = 0; i < TI; ++i) {
                    float4 v = make_float4(pi_r[i].x + c.x, pi_r[i].y + c.y,
                                           pi_r[i].z + c.z, pi_r[i].w + c.w);
                    __stcs(&out4[((size_t)i * SS + j) * E4 + e4], v);
                }
            }
        }
    }

    // ================= exit: last block resets flags (graph-replay safe) ===
    __syncthreads();
    if (tid == 0) {
        __threadfence();
        unsigned r = atomicAdd(&g_exit, 1);
        if (r == NBLK - 1) {
            g_arrive = 0;
            __threadfence();
            g_exit = 0;
        }
    }
}

// ---------------------------------------------------------------------------
extern "C" void kernel_launch(void* const* d_in, const int* in_sizes, int n_in,
                              void* d_out, int out_size)
{
    const float* x    = (const float*)d_in[0];   // component_repr [4,256,256]
    const float* W    = (const float*)d_in[1];   // W [256,512]
    const float* bias = (const float*)d_in[2];   // b [256]
    float* out = (float*)d_out;                  // [4,256,256,256]

    fused_kernel<<<NBLK, 256>>>(x, W, bias, out);
}

// round 6
// speedup vs baseline: 1.0582x; 1.0582x over previous
#include <cuda_runtime.h>

// Problem shape (fixed by the dataset)
#define BB 4
#define SS 256
#define EE 256
#define MM (BB * SS)

// Scratch: pi[m,f] and (pj[m,f] + b[f]) — 1 MB each
__device__ float g_pi [MM * EE];
__device__ float g_pjb[MM * EE];

// ---------------------------------------------------------------------------
// Kernel 1: dual GEMM with packed fma.rn.f32x2 (2 MACs/issue slot).
//   pi[m,f]  = sum_e x[m,e] * W[f,e]
//   pjb[m,f] = sum_e x[m,e] * W[f,EE+e] + b[f]
// 256 blocks x 256 threads, one BM(16) x BN(64) tile per block, BK=32,
// register-prefetch pipelining. Triggers PDL so the add kernel launches early.
// ---------------------------------------------------------------------------
#define BM 16
#define BN 64
#define BK 32
#define NT (EE / BK)        // 8 K-chunks
#define XS 20               // s_x row stride (floats)
#define WS 68               // s_w row stride (floats), 272B = 16B-aligned

__device__ __forceinline__ void fma2(unsigned long long& acc,
                                     unsigned long long a,
                                     unsigned long long b)
{
    asm("fma.rn.f32x2 %0, %1, %2, %0;" : "+l"(acc) : "l"(a), "l"(b));
}

__device__ __forceinline__ unsigned long long bcast2(float a)
{
    unsigned long long r;
    asm("mov.b64 %0, {%1, %1};" : "=l"(r) : "r"(__float_as_int(a)));
    return r;
}

__global__ __launch_bounds__(256)
void gemm_kernel(const float* __restrict__ x,
                 const float* __restrict__ W,
                 const float* __restrict__ bias)
{
    __shared__ float s_x [BK][XS];     // 2.5 KB
    __shared__ float s_w1[BK][WS];     // 8.7 KB
    __shared__ float s_w2[BK][WS];     // 8.7 KB

#if __CUDA_ARCH__ >= 900
    cudaTriggerProgrammaticLaunchCompletion();
#endif

    const int tid = threadIdx.x;
    const int bid = blockIdx.x;
    const int f0  = (bid & 3) * BN;
    const int m0  = (bid >> 2) * BM;

    const int  lkv   = tid & 7;        // k-float4 within chunk
    const int  lm    = tid >> 3;       // x row (tid<128 only)
    const int  lf    = tid >> 3;       // W row base (0..31; +32 for r=1)
    const bool xload = (tid < 128);

    const int m  = tid >> 4;           // 0..15 output m row
    const int fx = tid & 15;           // output f group (4 floats)

    float4 rx = make_float4(0.f, 0.f, 0.f, 0.f);
    float4 rw1[2], rw2[2];

    // prologue: chunk 0 -> regs
    if (xload)
        rx = *(const float4*)&x[(size_t)(m0 + lm) * EE + lkv * 4];
    #pragma unroll
    for (int r = 0; r < 2; ++r) {
        const float* wrow = W + (size_t)(f0 + lf + r * 32) * (2 * EE) + lkv * 4;
        rw1[r] = *(const float4*)(wrow);
        rw2[r] = *(const float4*)(wrow + EE);
    }

    unsigned long long acc[4] = {0ull, 0ull, 0ull, 0ull};

    for (int t = 0; t < NT; ++t) {
        if (t > 0) __syncthreads();
        if (xload) {
            s_x[lkv * 4 + 0][lm] = rx.x;
            s_x[lkv * 4 + 1][lm] = rx.y;
            s_x[lkv * 4 + 2][lm] = rx.z;
            s_x[lkv * 4 + 3][lm] = rx.w;
        }
        #pragma unroll
        for (int r = 0; r < 2; ++r) {
            int f = lf + r * 32;
            s_w1[lkv * 4 + 0][f] = rw1[r].x;
            s_w1[lkv * 4 + 1][f] = rw1[r].y;
            s_w1[lkv * 4 + 2][f] = rw1[r].z;
            s_w1[lkv * 4 + 3][f] = rw1[r].w;
            s_w2[lkv * 4 + 0][f] = rw2[r].x;
            s_w2[lkv * 4 + 1][f] = rw2[r].y;
            s_w2[lkv * 4 + 2][f] = rw2[r].z;
            s_w2[lkv * 4 + 3][f] = rw2[r].w;
        }
        __syncthreads();

        if (t + 1 < NT) {   // prefetch next chunk
            const int k0 = (t + 1) * BK;
            if (xload)
                rx = *(const float4*)&x[(size_t)(m0 + lm) * EE + k0 + lkv * 4];
            #pragma unroll
            for (int r = 0; r < 2; ++r) {
                const float* wrow = W + (size_t)(f0 + lf + r * 32) * (2 * EE) + k0 + lkv * 4;
                rw1[r] = *(const float4*)(wrow);
                rw2[r] = *(const float4*)(wrow + EE);
            }
        }

        #pragma unroll
        for (int k = 0; k < BK; ++k) {
            unsigned long long aa = bcast2(s_x[k][m]);
            const ulonglong2 b1 = *(const ulonglong2*)&s_w1[k][fx * 4];
            const ulonglong2 b2 = *(const ulonglong2*)&s_w2[k][fx * 4];
            fma2(acc[0], aa, b1.x);
            fma2(acc[1], aa, b1.y);
            fma2(acc[2], aa, b2.x);
            fma2(acc[3], aa, b2.y);
        }
    }

    float2 a0 = *(float2*)&acc[0];
    float2 a1 = *(float2*)&acc[1];
    float2 a2 = *(float2*)&acc[2];
    float2 a3 = *(float2*)&acc[3];
    float4 bi = *(const float4*)&bias[f0 + fx * 4];

    const size_t o = (size_t)(m0 + m) * EE + f0 + fx * 4;
    *(float4*)&g_pi [o] = make_float4(a0.x, a0.y, a1.x, a1.y);
    *(float4*)&g_pjb[o] = make_float4(a2.x + bi.x, a2.y + bi.y,
                                      a3.x + bi.z, a3.y + bi.w);
}

// ---------------------------------------------------------------------------
// Kernel 2: broadcast add (R2-proven body) — DRAM-write-bound.
// Launched with PDL: setup overlaps gemm tail; sync before touching scratch.
// ---------------------------------------------------------------------------
#define TI 8
#define TJ 32
#define E4 (EE / 4)

__global__ __launch_bounds__(256)
void add_kernel(float* __restrict__ out)
{
    __shared__ float4 s_pj[TJ * E4];   // 32 KB

    const int b   = blockIdx.z;
    const int i0  = blockIdx.y * TI;
    const int j0  = blockIdx.x * TJ;
    const int tid = threadIdx.x;
    const int e4  = tid & 63;
    const int jq  = tid >> 6;

    const float4* pi4 = (const float4*)g_pi  + (size_t)(b * SS + i0) * E4;
    const float4* pj4 = (const float4*)g_pjb + (size_t)(b * SS + j0) * E4;
    float4* out4 = (float4*)out + ((size_t)(b * SS + i0) * SS + j0) * E4;

#if __CUDA_ARCH__ >= 900
    cudaGridDependencySynchronize();   // gemm results now visible
#endif

    #pragma unroll
    for (int r = 0; r < 8; ++r)
        s_pj[tid + r * 256] = pj4[tid + r * 256];

    float4 pi_r[TI];
    #pragma unroll
    for (int i = 0; i < TI; ++i)
        pi_r[i] = pi4[i * E4 + e4];

    __syncthreads();

    #pragma unroll
    for (int jj = 0; jj < TJ / 4; ++jj) {
        int j = jq + jj * 4;
        float4 c = s_pj[j * E4 + e4];
        #pragma unroll
        for (int i = 0; i < TI; ++i) {
            float4 v = make_float4(pi_r[i].x + c.x, pi_r[i].y + c.y,
                                   pi_r[i].z + c.z, pi_r[i].w + c.w);
            __stcs(&out4[((size_t)i * SS + j) * E4 + e4], v);
        }
    }
}

// ---------------------------------------------------------------------------
extern "C" void kernel_launch(void* const* d_in, const int* in_sizes, int n_in,
                              void* d_out, int out_size)
{
    const float* x    = (const float*)d_in[0];   // component_repr [4,256,256]
    const float* W    = (const float*)d_in[1];   // W [256,512]
    const float* bias = (const float*)d_in[2];   // b [256]
    float* out = (float*)d_out;                  // [4,256,256,256]

    gemm_kernel<<<(MM / BM) * (EE / BN), 256>>>(x, W, bias);   // 256 blocks

    // Secondary launch with programmatic dependent launch (PDL)
    cudaLaunchConfig_t cfg = {};
    cfg.gridDim  = dim3(SS / TJ, SS / TI, BB);   // 8 x 32 x 4
    cfg.blockDim = dim3(256, 1, 1);
    cudaLaunchAttribute attr[1];
    attr[0].id = cudaLaunchAttributeProgrammaticStreamSerialization;
    attr[0].val.programmaticStreamSerializationAllowed = 1;
    cfg.attrs = attr;
    cfg.numAttrs = 1;
    cudaLaunchKernelEx(&cfg, add_kernel, out);
}

// round 7
// speedup vs baseline: 1.2530x; 1.1841x over previous
#include <cuda_runtime.h>

// Problem shape (fixed by the dataset)
#define BB 4
#define SS 256
#define EE 256
#define MM (BB * SS)

// Scratch: pi[m,f] and (pj[m,f] + b[f]) — 1 MB each
__device__ float g_pi [MM * EE];
__device__ float g_pjb[MM * EE];

// ---------------------------------------------------------------------------
// Kernel 1: dual GEMM — R2's proven skeleton (128 blocks x 256 thr, BM=32,
// BN=64, BK=32, double-buffered smem + register prefetch) with packed
// fma.rn.f32x2 accumulators (2 MACs per fma-pipe issue slot).
// ---------------------------------------------------------------------------
#define BM 32
#define BN 64
#define BK 32
#define NT (EE / BK)       // 8 K-chunks

#define XS 40              // s_x row stride (floats)
#define WS 68              // s_w row stride (floats): 272B, 16B-aligned

__device__ __forceinline__ void fma2(unsigned long long& acc,
                                     unsigned long long a,
                                     unsigned long long b)
{
    asm("fma.rn.f32x2 %0, %1, %2, %0;" : "+l"(acc) : "l"(a), "l"(b));
}

__device__ __forceinline__ unsigned long long bcast2(float a)
{
    unsigned long long r;
    asm("mov.b64 %0, {%1, %1};" : "=l"(r) : "r"(__float_as_int(a)));
    return r;
}

__global__ __launch_bounds__(256)
void gemm_kernel(const float* __restrict__ x,
                 const float* __restrict__ W,
                 const float* __restrict__ bias)
{
    __shared__ float s_x [2][BK][XS];
    __shared__ float s_w1[2][BK][WS];
    __shared__ float s_w2[2][BK][WS];

    const int m0  = blockIdx.x * BM;
    const int f0  = blockIdx.y * BN;
    const int tid = threadIdx.x;
    const int ty  = tid >> 4;    // 0..15 -> m (2 rows each)
    const int tx  = tid & 15;    // 0..15 -> f (4 cols = 2 f32x2 pairs)

    const int lm  = tid >> 3;    // 0..31  (x tile row)
    const int lkv = tid & 7;     // k-float4 within row
    const int lf  = tid >> 3;    // 0..31  (W row base; +32 with r=1)

    float4 rx, rw1[2], rw2[2];

    // ---- prologue: chunk 0 -> regs ----
    rx = *(const float4*)&x[(size_t)(m0 + lm) * EE + lkv * 4];
    #pragma unroll
    for (int r = 0; r < 2; ++r) {
        const float* wrow = W + (size_t)(f0 + lf + r * 32) * (2 * EE) + lkv * 4;
        rw1[r] = *(const float4*)(wrow);
        rw2[r] = *(const float4*)(wrow + EE);
    }
    // ---- store chunk 0 to buffer 0 ----
    {
        s_x[0][lkv * 4 + 0][lm] = rx.x;
        s_x[0][lkv * 4 + 1][lm] = rx.y;
        s_x[0][lkv * 4 + 2][lm] = rx.z;
        s_x[0][lkv * 4 + 3][lm] = rx.w;
        #pragma unroll
        for (int r = 0; r < 2; ++r) {
            int f = lf + r * 32;
            s_w1[0][lkv * 4 + 0][f] = rw1[r].x;
            s_w1[0][lkv * 4 + 1][f] = rw1[r].y;
            s_w1[0][lkv * 4 + 2][f] = rw1[r].z;
            s_w1[0][lkv * 4 + 3][f] = rw1[r].w;
            s_w2[0][lkv * 4 + 0][f] = rw2[r].x;
            s_w2[0][lkv * 4 + 1][f] = rw2[r].y;
            s_w2[0][lkv * 4 + 2][f] = rw2[r].z;
            s_w2[0][lkv * 4 + 3][f] = rw2[r].w;
        }
    }
    __syncthreads();

    // packed accumulators: [m-row][f-pair]
    unsigned long long acc1[2][2] = {};
    unsigned long long acc2[2][2] = {};

    for (int t = 0; t < NT; ++t) {
        const int buf = t & 1;

        if (t + 1 < NT) {   // prefetch next chunk into registers
            const int k0 = (t + 1) * BK;
            rx = *(const float4*)&x[(size_t)(m0 + lm) * EE + k0 + lkv * 4];
            #pragma unroll
            for (int r = 0; r < 2; ++r) {
                const float* wrow = W + (size_t)(f0 + lf + r * 32) * (2 * EE) + k0 + lkv * 4;
                rw1[r] = *(const float4*)(wrow);
                rw2[r] = *(const float4*)(wrow + EE);
            }
        }

        #pragma unroll
        for (int k = 0; k < BK; ++k) {
            unsigned long long a0 = bcast2(s_x[buf][k][ty * 2 + 0]);
            unsigned long long a1 = bcast2(s_x[buf][k][ty * 2 + 1]);
            const ulonglong2 b1 = *(const ulonglong2*)&s_w1[buf][k][tx * 4];
            const ulonglong2 b2 = *(const ulonglong2*)&s_w2[buf][k][tx * 4];
            fma2(acc1[0][0], a0, b1.x); fma2(acc1[0][1], a0, b1.y);
            fma2(acc1[1][0], a1, b1.x); fma2(acc1[1][1], a1, b1.y);
            fma2(acc2[0][0], a0, b2.x); fma2(acc2[0][1], a0, b2.y);
            fma2(acc2[1][0], a1, b2.x); fma2(acc2[1][1], a1, b2.y);
        }

        if (t + 1 < NT) {   // drain prefetch regs into the other buffer
            const int nbuf = (t + 1) & 1;
            __syncthreads();
            s_x[nbuf][lkv * 4 + 0][lm] = rx.x;
            s_x[nbuf][lkv * 4 + 1][lm] = rx.y;
            s_x[nbuf][lkv * 4 + 2][lm] = rx.z;
            s_x[nbuf][lkv * 4 + 3][lm] = rx.w;
            #pragma unroll
            for (int r = 0; r < 2; ++r) {
                int f = lf + r * 32;
                s_w1[nbuf][lkv * 4 + 0][f] = rw1[r].x;
                s_w1[nbuf][lkv * 4 + 1][f] = rw1[r].y;
                s_w1[nbuf][lkv * 4 + 2][f] = rw1[r].z;
                s_w1[nbuf][lkv * 4 + 3][f] = rw1[r].w;
                s_w2[nbuf][lkv * 4 + 0][f] = rw2[r].x;
                s_w2[nbuf][lkv * 4 + 1][f] = rw2[r].y;
                s_w2[nbuf][lkv * 4 + 2][f] = rw2[r].z;
                s_w2[nbuf][lkv * 4 + 3][f] = rw2[r].w;
            }
            __syncthreads();
        }
    }

    float4 bi = *(const float4*)&bias[f0 + tx * 4];

    #pragma unroll
    for (int i = 0; i < 2; ++i) {
        int m = m0 + ty * 2 + i;
        float2 p0 = *(float2*)&acc1[i][0];
        float2 p1 = *(float2*)&acc1[i][1];
        float2 q0 = *(float2*)&acc2[i][0];
        float2 q1 = *(float2*)&acc2[i][1];
        *(float4*)&g_pi [(size_t)m * EE + f0 + tx * 4] =
            make_float4(p0.x, p0.y, p1.x, p1.y);
        *(float4*)&g_pjb[(size_t)m * EE + f0 + tx * 4] =
            make_float4(q0.x + bi.x, q0.y + bi.y, q1.x + bi.z, q1.y + bi.w);
    }
}

// ---------------------------------------------------------------------------
// Kernel 2: broadcast add. TI=4 halves register footprint (pi_r: 16 regs) so
// 5-6 CTAs/SM fit -> more resident warps -> more stores in flight.
// Grid: (256/32, 256/4, 4) = 8 x 64 x 4 = 2048 blocks, 256 threads.
// ---------------------------------------------------------------------------
#define TI 4
#define TJ 32
#define E4 (EE / 4)   // 64 float4 per row

__global__ __launch_bounds__(256)
void add_kernel(float* __restrict__ out)
{
    __shared__ float4 s_pj[TJ * E4];   // 32 KB

    const int b   = blockIdx.z;
    const int i0  = blockIdx.y * TI;
    const int j0  = blockIdx.x * TJ;
    const int tid = threadIdx.x;
    const int e4  = tid & 63;
    const int jq  = tid >> 6;

    const float4* pi4 = (const float4*)g_pi  + (size_t)(b * SS + i0) * E4;
    const float4* pj4 = (const float4*)g_pjb + (size_t)(b * SS + j0) * E4;

    #pragma unroll
    for (int r = 0; r < 8; ++r)
        s_pj[tid + r * 256] = pj4[tid + r * 256];

    float4 pi_r[TI];
    #pragma unroll
    for (int i = 0; i < TI; ++i)
        pi_r[i] = pi4[i * E4 + e4];

    __syncthreads();

    float4* out4 = (float4*)out + ((size_t)(b * SS + i0) * SS + j0) * E4;

    #pragma unroll
    for (int jj = 0; jj < TJ / 4; ++jj) {
        int j = jq + jj * 4;
        float4 c = s_pj[j * E4 + e4];
        #pragma unroll
        for (int i = 0; i < TI; ++i) {
            float4 v = make_float4(pi_r[i].x + c.x, pi_r[i].y + c.y,
                                   pi_r[i].z + c.z, pi_r[i].w + c.w);
            __stcs(&out4[((size_t)i * SS + j) * E4 + e4], v);
        }
    }
}

// ---------------------------------------------------------------------------
extern "C" void kernel_launch(void* const* d_in, const int* in_sizes, int n_in,
                              void* d_out, int out_size)
{
    const float* x    = (const float*)d_in[0];   // component_repr [4,256,256]
    const float* W    = (const float*)d_in[1];   // W [256,512]
    const float* bias = (const float*)d_in[2];   // b [256]
    float* out = (float*)d_out;                  // [4,256,256,256]

    dim3 gGemm(MM / BM, EE / BN);                // 32 x 4 = 128 blocks
    gemm_kernel<<<gGemm, 256>>>(x, W, bias);

    dim3 gAdd(SS / TJ, SS / TI, BB);             // 8 x 64 x 4 = 2048 blocks
    add_kernel<<<gAdd, 256>>>(out);
}

// round 8
// speedup vs baseline: 1.2819x; 1.0231x over previous
#include <cuda_runtime.h>

// Problem shape (fixed by the dataset)
#define BB 4
#define SS 256
#define EE 256
#define MM (BB * SS)

// Scratch: pi[m,f] and (pj[m,f] + b[f]) — 1 MB each
__device__ float g_pi [MM * EE];
__device__ float g_pjb[MM * EE];

// ---------------------------------------------------------------------------
// Kernel 1: dual GEMM — high arithmetic intensity version.
// 128 blocks x 128 threads. BM=32, BN=64, BK=32, thread tile 4m x 4f x 2mat.
// LDS per k per thread: 16B (a, one LDS.128) + 32B (W) for 32 MACs
// = 1.5 B/MAC (was 2.5). Packed fma.rn.f32x2 accumulators.
// ---------------------------------------------------------------------------
#define BM 32
#define BN 64
#define BK 32
#define NT (EE / BK)       // 8 K-chunks

#define XS 36              // s_x row stride (floats): 144B = 9*16 (16B-aligned)
#define WS 68              // s_w row stride (floats): 272B = 17*16 (16B-aligned)

__device__ __forceinline__ void fma2(unsigned long long& acc,
                                     unsigned long long a,
                                     unsigned long long b)
{
    asm("fma.rn.f32x2 %0, %1, %2, %0;" : "+l"(acc) : "l"(a), "l"(b));
}

__device__ __forceinline__ unsigned long long bcast2(float a)
{
    unsigned long long r;
    asm("mov.b64 %0, {%1, %1};" : "=l"(r) : "r"(__float_as_int(a)));
    return r;
}

__global__ __launch_bounds__(128)
void gemm_kernel(const float* __restrict__ x,
                 const float* __restrict__ W,
                 const float* __restrict__ bias)
{
    __shared__ float s_x [2][BK][XS];    //  9.2 KB
    __shared__ float s_w1[2][BK][WS];    // 17.4 KB
    __shared__ float s_w2[2][BK][WS];    // 17.4 KB

    const int m0  = blockIdx.x * BM;
    const int f0  = blockIdx.y * BN;
    const int tid = threadIdx.x;

    const int ty  = tid >> 4;    // 0..7  -> m (4 rows each)
    const int tx  = tid & 15;    // 0..15 -> f (4 cols = 2 f32x2 pairs)

    const int lr  = tid >> 3;    // 0..15 load row base
    const int lc  = tid & 7;     // k-float4 within row

    float4 rx[2], rw1[4], rw2[4];

    // ---- prologue: chunk 0 -> regs ----
    #pragma unroll
    for (int r = 0; r < 2; ++r)
        rx[r] = *(const float4*)&x[(size_t)(m0 + lr + r * 16) * EE + lc * 4];
    #pragma unroll
    for (int r = 0; r < 4; ++r) {
        const float* wrow = W + (size_t)(f0 + lr + r * 16) * (2 * EE) + lc * 4;
        rw1[r] = *(const float4*)(wrow);
        rw2[r] = *(const float4*)(wrow + EE);
    }
    // ---- store chunk 0 to buffer 0 (transpose to [k][row]) ----
    {
        #pragma unroll
        for (int r = 0; r < 2; ++r) {
            int m = lr + r * 16;
            s_x[0][lc * 4 + 0][m] = rx[r].x;
            s_x[0][lc * 4 + 1][m] = rx[r].y;
            s_x[0][lc * 4 + 2][m] = rx[r].z;
            s_x[0][lc * 4 + 3][m] = rx[r].w;
        }
        #pragma unroll
        for (int r = 0; r < 4; ++r) {
            int f = lr + r * 16;
            s_w1[0][lc * 4 + 0][f] = rw1[r].x;
            s_w1[0][lc * 4 + 1][f] = rw1[r].y;
            s_w1[0][lc * 4 + 2][f] = rw1[r].z;
            s_w1[0][lc * 4 + 3][f] = rw1[r].w;
            s_w2[0][lc * 4 + 0][f] = rw2[r].x;
            s_w2[0][lc * 4 + 1][f] = rw2[r].y;
            s_w2[0][lc * 4 + 2][f] = rw2[r].z;
            s_w2[0][lc * 4 + 3][f] = rw2[r].w;
        }
    }
    __syncthreads();

    // packed accumulators: [m-row 0..3][f-pair 0..1] per matrix
    unsigned long long acc1[4][2] = {};
    unsigned long long acc2[4][2] = {};

    for (int t = 0; t < NT; ++t) {
        const int buf = t & 1;

        if (t + 1 < NT) {   // prefetch next chunk into registers
            const int k0 = (t + 1) * BK;
            #pragma unroll
            for (int r = 0; r < 2; ++r)
                rx[r] = *(const float4*)&x[(size_t)(m0 + lr + r * 16) * EE + k0 + lc * 4];
            #pragma unroll
            for (int r = 0; r < 4; ++r) {
                const float* wrow = W + (size_t)(f0 + lr + r * 16) * (2 * EE) + k0 + lc * 4;
                rw1[r] = *(const float4*)(wrow);
                rw2[r] = *(const float4*)(wrow + EE);
            }
        }

        #pragma unroll
        for (int k = 0; k < BK; ++k) {
            float4 av = *(const float4*)&s_x[buf][k][ty * 4];
            unsigned long long a0 = bcast2(av.x);
            unsigned long long a1 = bcast2(av.y);
            unsigned long long a2 = bcast2(av.z);
            unsigned long long a3 = bcast2(av.w);
            const ulonglong2 b1 = *(const ulonglong2*)&s_w1[buf][k][tx * 4];
            const ulonglong2 b2 = *(const ulonglong2*)&s_w2[buf][k][tx * 4];

            fma2(acc1[0][0], a0, b1.x); fma2(acc1[0][1], a0, b1.y);
            fma2(acc1[1][0], a1, b1.x); fma2(acc1[1][1], a1, b1.y);
            fma2(acc1[2][0], a2, b1.x); fma2(acc1[2][1], a2, b1.y);
            fma2(acc1[3][0], a3, b1.x); fma2(acc1[3][1], a3, b1.y);

            fma2(acc2[0][0], a0, b2.x); fma2(acc2[0][1], a0, b2.y);
            fma2(acc2[1][0], a1, b2.x); fma2(acc2[1][1], a1, b2.y);
            fma2(acc2[2][0], a2, b2.x); fma2(acc2[2][1], a2, b2.y);
            fma2(acc2[3][0], a3, b2.x); fma2(acc2[3][1], a3, b2.y);
        }

        if (t + 1 < NT) {   // drain prefetch regs into the other buffer
            const int nbuf = (t + 1) & 1;
            __syncthreads();
            #pragma unroll
            for (int r = 0; r < 2; ++r) {
                int m = lr + r * 16;
                s_x[nbuf][lc * 4 + 0][m] = rx[r].x;
                s_x[nbuf][lc * 4 + 1][m] = rx[r].y;
                s_x[nbuf][lc * 4 + 2][m] = rx[r].z;
                s_x[nbuf][lc * 4 + 3][m] = rx[r].w;
            }
            #pragma unroll
            for (int r = 0; r < 4; ++r) {
                int f = lr + r * 16;
                s_w1[nbuf][lc * 4 + 0][f] = rw1[r].x;
                s_w1[nbuf][lc * 4 + 1][f] = rw1[r].y;
                s_w1[nbuf][lc * 4 + 2][f] = rw1[r].z;
                s_w1[nbuf][lc * 4 + 3][f] = rw1[r].w;
                s_w2[nbuf][lc * 4 + 0][f] = rw2[r].x;
                s_w2[nbuf][lc * 4 + 1][f] = rw2[r].y;
                s_w2[nbuf][lc * 4 + 2][f] = rw2[r].z;
                s_w2[nbuf][lc * 4 + 3][f] = rw2[r].w;
            }
            __syncthreads();
        }
    }

    float4 bi = *(const float4*)&bias[f0 + tx * 4];

    #pragma unroll
    for (int i = 0; i < 4; ++i) {
        int m = m0 + ty * 4 + i;
        float2 p0 = *(float2*)&acc1[i][0];
        float2 p1 = *(float2*)&acc1[i][1];
        float2 q0 = *(float2*)&acc2[i][0];
        float2 q1 = *(float2*)&acc2[i][1];
        *(float4*)&g_pi [(size_t)m * EE + f0 + tx * 4] =
            make_float4(p0.x, p0.y, p1.x, p1.y);
        *(float4*)&g_pjb[(size_t)m * EE + f0 + tx * 4] =
            make_float4(q0.x + bi.x, q0.y + bi.y, q1.x + bi.z, q1.y + bi.w);
    }
}

// ---------------------------------------------------------------------------
// Kernel 2: broadcast add (unchanged from R7: 2048 blocks, occ 52%, ~43us —
// at the DRAM-write ceiling for this pattern).
// ---------------------------------------------------------------------------
#define TI 4
#define TJ 32
#define E4 (EE / 4)   // 64 float4 per row

__global__ __launch_bounds__(256)
void add_kernel(float* __restrict__ out)
{
    __shared__ float4 s_pj[TJ * E4];   // 32 KB

    const int b   = blockIdx.z;
    const int i0  = blockIdx.y * TI;
    const int j0  = blockIdx.x * TJ;
    const int tid = threadIdx.x;
    const int e4  = tid & 63;
    const int jq  = tid >> 6;

    const float4* pi4 = (const float4*)g_pi  + (size_t)(b * SS + i0) * E4;
    const float4* pj4 = (const float4*)g_pjb + (size_t)(b * SS + j0) * E4;

    #pragma unroll
    for (int r = 0; r < 8; ++r)
        s_pj[tid + r * 256] = pj4[tid + r * 256];

    float4 pi_r[TI];
    #pragma unroll
    for (int i = 0; i < TI; ++i)
        pi_r[i] = pi4[i * E4 + e4];

    __syncthreads();

    float4* out4 = (float4*)out + ((size_t)(b * SS + i0) * SS + j0) * E4;

    #pragma unroll
    for (int jj = 0; jj < TJ / 4; ++jj) {
        int j = jq + jj * 4;
        float4 c = s_pj[j * E4 + e4];
        #pragma unroll
        for (int i = 0; i < TI; ++i) {
            float4 v = make_float4(pi_r[i].x + c.x, pi_r[i].y + c.y,
                                   pi_r[i].z + c.z, pi_r[i].w + c.w);
            __stcs(&out4[((size_t)i * SS + j) * E4 + e4], v);
        }
    }
}

// ---------------------------------------------------------------------------
extern "C" void kernel_launch(void* const* d_in, const int* in_sizes, int n_in,
                              void* d_out, int out_size)
{
    const float* x    = (const float*)d_in[0];   // component_repr [4,256,256]
    const float* W    = (const float*)d_in[1];   // W [256,512]
    const float* bias = (const float*)d_in[2];   // b [256]
    float* out = (float*)d_out;                  // [4,256,256,256]

    dim3 gGemm(MM / BM, EE / BN);                // 32 x 4 = 128 blocks
    gemm_kernel<<<gGemm, 128>>>(x, W, bias);

    dim3 gAdd(SS / TJ, SS / TI, BB);             // 8 x 64 x 4 = 2048 blocks
    add_kernel<<<gAdd, 256>>>(out);
}

// round 10
// speedup vs baseline: 1.3464x; 1.0503x over previous
#include <cuda_runtime.h>

// Problem shape (fixed by the dataset)
#define BB 4
#define SS 256
#define EE 256
#define MM (BB * SS)

// Scratch: pi[m,f] and (pj[m,f] + b[f]) — 1 MB each
__device__ float g_pi [MM * EE];
__device__ float g_pjb[MM * EE];

// ---------------------------------------------------------------------------
// Kernel 1: dual GEMM, single-load / sync-free mainloop.
// 128 blocks x 128 threads, BM=32, BN=64, full K=256 resident in SMEM (~173KB
// dynamic). Thread tile 4m x 4f x 2mat, packed fma.rn.f32x2.
// Exactly ONE __syncthreads; the k-loop has no barriers and no double
// buffering, so the compiler can pipeline LDS arbitrarily far ahead.
// ---------------------------------------------------------------------------
#define BM 32
#define BN 64

#define XSTR 260                 // s_x row stride (floats): 1040B = 65*16 (16B-aligned!)
#define WSTR 68                  // s_w row stride (floats): 272B = 17*16

#define SX_FLOATS (BM * XSTR)                 //  8320
#define SW_FLOATS (EE * WSTR)                 // 17408
#define SMEM_FLOATS (SX_FLOATS + 2 * SW_FLOATS)
#define SMEM_BYTES (SMEM_FLOATS * 4)          // 172,544 B

__device__ __forceinline__ void fma2(unsigned long long& acc,
                                     unsigned long long a,
                                     unsigned long long b)
{
    asm("fma.rn.f32x2 %0, %1, %2, %0;" : "+l"(acc) : "l"(a), "l"(b));
}

__device__ __forceinline__ unsigned long long bcast2(float a)
{
    unsigned long long r;
    asm("mov.b64 %0, {%1, %1};" : "=l"(r) : "r"(__float_as_int(a)));
    return r;
}

__global__ __launch_bounds__(128)
void gemm_kernel(const float* __restrict__ x,
                 const float* __restrict__ W,
                 const float* __restrict__ bias)
{
    extern __shared__ float sm[];
    float* s_x  = sm;                         // [BM][XSTR]  (m-major, direct copy)
    float* s_w1 = sm + SX_FLOATS;             // [EE][WSTR]  (k-major, transposed)
    float* s_w2 = sm + SX_FLOATS + SW_FLOATS;

    const int m0  = blockIdx.x * BM;
    const int f0  = blockIdx.y * BN;
    const int tid = threadIdx.x;

    const int ty  = tid >> 4;    // 0..7  -> m (4 rows each)
    const int tx  = tid & 15;    // 0..15 -> f (4 cols = 2 f32x2 pairs)

    // ---------------- load x: direct copy [m][k], coalesced -----------------
    #pragma unroll
    for (int i = 0; i < 16; ++i) {
        int idx = tid + i * 128;              // 0..2047
        int row = idx >> 6;                   // m 0..31
        int c4  = idx & 63;                   // k-float4 0..63
        float4 v = *(const float4*)&x[(size_t)(m0 + row) * EE + c4 * 4];
        *(float4*)&s_x[row * XSTR + c4 * 4] = v;
    }

    // ---------------- load W: 4x4 register transpose -> [k][f] --------------
    // 1024 4x4 tiles per matrix (16 f-groups x 64 k-groups), 8 per thread.
    #pragma unroll
    for (int i = 0; i < 8; ++i) {
        int t4 = tid + i * 128;               // 0..1023
        int fg = t4 >> 6;                     // f-group 0..15
        int kg = t4 & 63;                     // k-group 0..63
        const float* wb = W + (size_t)(f0 + fg * 4) * (2 * EE) + kg * 4;

        float4 a0 = *(const float4*)(wb + 0 * (2 * EE));
        float4 a1 = *(const float4*)(wb + 1 * (2 * EE));
        float4 a2 = *(const float4*)(wb + 2 * (2 * EE));
        float4 a3 = *(const float4*)(wb + 3 * (2 * EE));
        float* d1 = s_w1 + (kg * 4) * WSTR + fg * 4;
        *(float4*)(d1 + 0 * WSTR) = make_float4(a0.x, a1.x, a2.x, a3.x);
        *(float4*)(d1 + 1 * WSTR) = make_float4(a0.y, a1.y, a2.y, a3.y);
        *(float4*)(d1 + 2 * WSTR) = make_float4(a0.z, a1.z, a2.z, a3.z);
        *(float4*)(d1 + 3 * WSTR) = make_float4(a0.w, a1.w, a2.w, a3.w);

        float4 b0 = *(const float4*)(wb + EE + 0 * (2 * EE));
        float4 b1 = *(const float4*)(wb + EE + 1 * (2 * EE));
        float4 b2 = *(const float4*)(wb + EE + 2 * (2 * EE));
        float4 b3 = *(const float4*)(wb + EE + 3 * (2 * EE));
        float* d2 = s_w2 + (kg * 4) * WSTR + fg * 4;
        *(float4*)(d2 + 0 * WSTR) = make_float4(b0.x, b1.x, b2.x, b3.x);
        *(float4*)(d2 + 1 * WSTR) = make_float4(b0.y, b1.y, b2.y, b3.y);
        *(float4*)(d2 + 2 * WSTR) = make_float4(b0.z, b1.z, b2.z, b3.z);
        *(float4*)(d2 + 3 * WSTR) = make_float4(b0.w, b1.w, b2.w, b3.w);
    }

    __syncthreads();   // the only barrier

    // ---------------- sync-free mainloop over full K ------------------------
    unsigned long long acc1[4][2] = {};
    unsigned long long acc2[4][2] = {};

    const float* ax0 = s_x + (ty * 4 + 0) * XSTR;
    const float* ax1 = s_x + (ty * 4 + 1) * XSTR;
    const float* ax2 = s_x + (ty * 4 + 2) * XSTR;
    const float* ax3 = s_x + (ty * 4 + 3) * XSTR;

    #pragma unroll 1
    for (int ko = 0; ko < EE; ko += 16) {
        #pragma unroll
        for (int k2 = 0; k2 < 16; ++k2) {
            const int k = ko + k2;
            unsigned long long a0 = bcast2(ax0[k]);   // broadcast LDS.32
            unsigned long long a1 = bcast2(ax1[k]);
            unsigned long long a2 = bcast2(ax2[k]);
            unsigned long long a3 = bcast2(ax3[k]);
            const ulonglong2 w1 = *(const ulonglong2*)&s_w1[k * WSTR + tx * 4];
            const ulonglong2 w2 = *(const ulonglong2*)&s_w2[k * WSTR + tx * 4];

            fma2(acc1[0][0], a0, w1.x); fma2(acc1[0][1], a0, w1.y);
            fma2(acc1[1][0], a1, w1.x); fma2(acc1[1][1], a1, w1.y);
            fma2(acc1[2][0], a2, w1.x); fma2(acc1[2][1], a2, w1.y);
            fma2(acc1[3][0], a3, w1.x); fma2(acc1[3][1], a3, w1.y);

            fma2(acc2[0][0], a0, w2.x); fma2(acc2[0][1], a0, w2.y);
            fma2(acc2[1][0], a1, w2.x); fma2(acc2[1][1], a1, w2.y);
            fma2(acc2[2][0], a2, w2.x); fma2(acc2[2][1], a2, w2.y);
            fma2(acc2[3][0], a3, w2.x); fma2(acc2[3][1], a3, w2.y);
        }
    }

    // ---------------- epilogue ---------------------------------------------
    float4 bi = *(const float4*)&bias[f0 + tx * 4];

    #pragma unroll
    for (int i = 0; i < 4; ++i) {
        int m = m0 + ty * 4 + i;
        float2 p0 = *(float2*)&acc1[i][0];
        float2 p1 = *(float2*)&acc1[i][1];
        float2 q0 = *(float2*)&acc2[i][0];
        float2 q1 = *(float2*)&acc2[i][1];
        *(float4*)&g_pi [(size_t)m * EE + f0 + tx * 4] =
            make_float4(p0.x, p0.y, p1.x, p1.y);
        *(float4*)&g_pjb[(size_t)m * EE + f0 + tx * 4] =
            make_float4(q0.x + bi.x, q0.y + bi.y, q1.x + bi.z, q1.y + bi.w);
    }
}

// ---------------------------------------------------------------------------
// Kernel 2: broadcast add (unchanged R7: 2048 blocks, ~43us — at the
// DRAM-write ceiling for this pattern).
// ---------------------------------------------------------------------------
#define TI 4
#define TJ 32
#define E4 (EE / 4)

__global__ __launch_bounds__(256)
void add_kernel(float* __restrict__ out)
{
    __shared__ float4 s_pj[TJ * E4];   // 32 KB

    const int b   = blockIdx.z;
    const int i0  = blockIdx.y * TI;
    const int j0  = blockIdx.x * TJ;
    const int tid = threadIdx.x;
    const int e4  = tid & 63;
    const int jq  = tid >> 6;

    const float4* pi4 = (const float4*)g_pi  + (size_t)(b * SS + i0) * E4;
    const float4* pj4 = (const float4*)g_pjb + (size_t)(b * SS + j0) * E4;

    #pragma unroll
    for (int r = 0; r < 8; ++r)
        s_pj[tid + r * 256] = pj4[tid + r * 256];

    float4 pi_r[TI];
    #pragma unroll
    for (int i = 0; i < TI; ++i)
        pi_r[i] = pi4[i * E4 + e4];

    __syncthreads();

    float4* out4 = (float4*)out + ((size_t)(b * SS + i0) * SS + j0) * E4;

    #pragma unroll
    for (int jj = 0; jj < TJ / 4; ++jj) {
        int j = jq + jj * 4;
        float4 c = s_pj[j * E4 + e4];
        #pragma unroll
        for (int i = 0; i < TI; ++i) {
            float4 v = make_float4(pi_r[i].x + c.x, pi_r[i].y + c.y,
                                   pi_r[i].z + c.z, pi_r[i].w + c.w);
            __stcs(&out4[((size_t)i * SS + j) * E4 + e4], v);
        }
    }
}

// ---------------------------------------------------------------------------
extern "C" void kernel_launch(void* const* d_in, const int* in_sizes, int n_in,
                              void* d_out, int out_size)
{
    const float* x    = (const float*)d_in[0];   // component_repr [4,256,256]
    const float* W    = (const float*)d_in[1];   // W [256,512]
    const float* bias = (const float*)d_in[2];   // b [256]
    float* out = (float*)d_out;                  // [4,256,256,256]

    // raise dynamic smem cap (idempotent; attribute set, not an allocation)
    cudaFuncSetAttribute(gemm_kernel,
                         cudaFuncAttributeMaxDynamicSharedMemorySize,
                         SMEM_BYTES);

    dim3 gGemm(MM / BM, EE / BN);                // 32 x 4 = 128 blocks
    gemm_kernel<<<gGemm, 128, SMEM_BYTES>>>(x, W, bias);

    dim3 gAdd(SS / TJ, SS / TI, BB);             // 8 x 64 x 4 = 2048 blocks
    add_kernel<<<gAdd, 256>>>(out);
}